// round 9
// baseline (speedup 1.0000x reference)
#include <cuda_runtime.h>
#include <math.h>

#define T_LEN    3000
#define C_CH     1024
#define KSIZE    24
#define SEG      1000          // outputs per CTA (third of a row)
#define NSEG     3
#define THREADS  128
#define NGROUP   (SEG / 8)     // 125 groups of 8 consecutive outputs

// s (1024 floats = 256 float4 chunks): s[i] = x[segbase + i - 24].
// Output j uses s[j+1 .. j+24]; thread/group g loads chunks 2g..2g+7
// (floats 8g..8g+31; float 8g never contributes).
// Chunk swizzle c' = c ^ ((c>>3)&1): conflict-free for both the contiguous
// staging stores and the 32B-lane-stride window loads (adjacent 8-chunk
// groups flip bank parity, so each 8-lane phase hits 8 distinct banks).
#define NCHUNK 256
__device__ __forceinline__ int swzc(int c) { return c ^ ((c >> 3) & 1); }

__global__ __launch_bounds__(THREADS, 10)
void ssm4d_conv_kernel(const float* __restrict__ x,
                       const float* __restrict__ alpha,
                       const float* __restrict__ beta,
                       const float* __restrict__ theta,
                       float* __restrict__ y)
{
    __shared__ __align__(16) float4 S4[NCHUNK];
    __shared__ float wsh[KSIZE];

    const int row = blockIdx.x / NSEG;        // row = b*C + c
    const int seg = blockIdx.x - row * NSEG;  // 0..2
    const int c   = row & (C_CH - 1);
    const int tid = threadIdx.x;

    const int segBase = seg * SEG;
    // x4 points at x[segbase - 24] viewed as float4 (16B-aligned: segbase and
    // row offsets are multiples of 4 floats).
    const float4* __restrict__ x4 =
        reinterpret_cast<const float4*>(x + (size_t)row * T_LEN + segBase - 24);
    float* __restrict__ yseg = y + (size_t)row * T_LEN + segBase;

    // Synthesize the 24 depthwise taps for this channel (once per block).
    // w[k] = beta * exp(log(max(alpha,1e-6))*k) * (1 - (theta*k)^2/2 + (theta*k)^4/24)
    if (tid < KSIZE) {
        float a   = fmaxf(alpha[c], 1e-6f);
        float la  = logf(a);
        float k   = (float)tid;
        float dec = expf(la * k);
        float xx  = theta[c] * k;
        float x2  = xx * xx;
        float ph  = 1.0f - 0.5f * x2 + (x2 * x2) * (1.0f / 24.0f);
        wsh[tid]  = beta[c] * dec * ph;
    }

    // Stage exactly 256 chunks: chunks 0..5 = halo x[segbase-24..-1]
    // (zeros for seg 0), chunks 6..255 = x[segbase .. segbase+999].
    // 2 LDG.128 + 2 swizzled STS.128 per thread, fully coalesced.
    #pragma unroll
    for (int u = 0; u < 2; u++) {
        const int ch = tid + u * THREADS;
        float4 v;
        if (seg == 0 && ch < 6) v = make_float4(0.f, 0.f, 0.f, 0.f);
        else                    v = x4[ch];
        S4[swzc(ch)] = v;
    }

    __syncthreads();

    if (tid < NGROUP) {    // 125 active threads, one 8-output group each
        // Weights to registers (LDS broadcast, conflict-free).
        float w[KSIZE];
        #pragma unroll
        for (int k = 0; k < KSIZE; k++) w[k] = wsh[k];

        const int g  = tid;
        const int c0 = 2 * g;          // first window chunk

        float acc[8];
        #pragma unroll
        for (int j = 0; j < 8; j++) acc[j] = 0.0f;

        // Chunk-consume the 32-float window: local float m (1..31) feeds
        // acc[j] with tap k = m - j - 1 for j in [max(0,m-24), min(7,m-1)].
        // 192 FFMA, 8 LDS.128.
        #pragma unroll
        for (int q = 0; q < 8; q++) {
            const float4 v = S4[swzc(c0 + q)];
            #pragma unroll
            for (int i = 0; i < 4; i++) {
                const int m = 4 * q + i;
                const float xv = (i == 0) ? v.x : (i == 1) ? v.y
                               : (i == 2) ? v.z : v.w;
                #pragma unroll
                for (int j = 0; j < 8; j++) {
                    const int k = m - j - 1;
                    if (k >= 0 && k < KSIZE)
                        acc[j] = fmaf(w[k], xv, acc[j]);
                }
            }
        }

        // Store 8 consecutive outputs: 2x STG.128 (warp pair covers a
        // contiguous 1024B span between them).
        *reinterpret_cast<float4*>(&yseg[8 * g]) =
            make_float4(acc[0], acc[1], acc[2], acc[3]);
        *reinterpret_cast<float4*>(&yseg[8 * g + 4]) =
            make_float4(acc[4], acc[5], acc[6], acc[7]);
    }
}

extern "C" void kernel_launch(void* const* d_in, const int* in_sizes, int n_in,
                              void* d_out, int out_size)
{
    const float* x     = (const float*)d_in[0];
    const float* alpha = (const float*)d_in[1];
    const float* beta  = (const float*)d_in[2];
    const float* theta = (const float*)d_in[3];
    float* y = (float*)d_out;

    const int rows = in_sizes[0] / T_LEN;   // B*C = 16384
    ssm4d_conv_kernel<<<rows * NSEG, THREADS>>>(x, alpha, beta, theta, y);
}

// round 11
// speedup vs baseline: 1.7668x; 1.7668x over previous
#include <cuda_runtime.h>
#include <math.h>
#include <stdint.h>

#define T_LEN    3000
#define C_CH     1024
#define KSIZE    24
#define SEG      1500          // outputs per CTA (half a row)
#define THREADS  128
#define NGROUP   (SEG / 4)     // 375 groups of 4 consecutive outputs

// Layout: s[i] = x[segBase + i - 24]; s[0] unused, halo s[1..23], data
// s[24..1523]. Output 4g+j = sum_k w[k]*s[4g + (k+j+1)]; group g reads
// float4 chunks g..g+6 (s[4g..4g+27]) -- all 16B-aligned, affine offsets.
#define SBUF_FLOATS 1536       // chunks 0..383 (data ends at chunk 380)
#define DATA_CHUNK0 6          // chunk of s[24]
#define NDATA_CHUNK 375        // 1500 floats

__global__ __launch_bounds__(THREADS, 12)
void ssm4d_conv_kernel(const float* __restrict__ x,
                       const float* __restrict__ alpha,
                       const float* __restrict__ beta,
                       const float* __restrict__ theta,
                       float* __restrict__ y)
{
    __shared__ __align__(16) float s[SBUF_FLOATS];
    __shared__ float wsh[KSIZE];

    const int row  = blockIdx.x >> 1;        // row = b*C + c
    const int half = blockIdx.x & 1;
    const int c    = row & (C_CH - 1);
    const int tid  = threadIdx.x;

    const float* __restrict__ xseg = x + (size_t)row * T_LEN + half * SEG;
    float* __restrict__       yseg = y + (size_t)row * T_LEN + half * SEG;

    // Vectorized staging: 375 aligned 16B cp.async per CTA (3 per thread).
    {
        uint32_t sa;
        asm("{ .reg .u64 t; cvta.to.shared.u64 t, %1; cvt.u32.u64 %0, t; }"
            : "=r"(sa) : "l"(s + 4 * DATA_CHUNK0));
        #pragma unroll
        for (int u = 0; u < 3; u++) {
            const int ch = tid + u * THREADS;
            if (ch < NDATA_CHUNK) {
                asm volatile("cp.async.cg.shared.global [%0], [%1], 16;"
                             :: "r"(sa + 16u * ch), "l"(xseg + 4 * ch));
            }
        }
        asm volatile("cp.async.commit_group;");
    }

    // Halo s[1..23]: zeros for the first half, real data for the second.
    if (tid < KSIZE - 1)
        s[1 + tid] = half ? xseg[tid - 23] : 0.0f;

    // Synthesize the 24 depthwise taps for this channel (once per block).
    // w[k] = beta * exp(log(max(alpha,1e-6))*k) * (1 - (theta*k)^2/2 + (theta*k)^4/24)
    if (tid < KSIZE) {
        float a   = fmaxf(alpha[c], 1e-6f);
        float la  = logf(a);
        float k   = (float)tid;
        float dec = expf(la * k);
        float xx  = theta[c] * k;
        float x2  = xx * xx;
        float ph  = 1.0f - 0.5f * x2 + (x2 * x2) * (1.0f / 24.0f);
        wsh[tid]  = beta[c] * dec * ph;
    }

    asm volatile("cp.async.wait_group 0;");
    __syncthreads();

    // Weights to registers (LDS broadcast, conflict-free).
    float w[KSIZE];
    #pragma unroll
    for (int k = 0; k < KSIZE; k++) w[k] = wsh[k];

    // Each thread: groups g = tid, tid+128, tid+256 (g < 375). 16B lane
    // stride -> every LDS.128 is a contiguous conflict-free 512B warp
    // access; STG.128 stores are perfectly coalesced.
    #pragma unroll
    for (int gi = 0; gi < 3; gi++) {
        const int g = tid + gi * THREADS;
        if (g < NGROUP) {
            const float* sp = &s[4 * g];

            float a0 = 0.f, a1 = 0.f, a2 = 0.f, a3 = 0.f;
            #pragma unroll
            for (int q = 0; q < 7; q++) {
                float4 v = *reinterpret_cast<const float4*>(sp + 4 * q);
                #pragma unroll
                for (int i = 0; i < 4; i++) {
                    const int m = 4 * q + i;            // window index
                    const float xv = (i == 0) ? v.x : (i == 1) ? v.y
                                   : (i == 2) ? v.z : v.w;
                    // acc j uses tap k = m - j - 1, valid for 0 <= k < 24.
                    { const int k = m - 1; if (k >= 0 && k < KSIZE) a0 = fmaf(w[k], xv, a0); }
                    { const int k = m - 2; if (k >= 0 && k < KSIZE) a1 = fmaf(w[k], xv, a1); }
                    { const int k = m - 3; if (k >= 0 && k < KSIZE) a2 = fmaf(w[k], xv, a2); }
                    { const int k = m - 4; if (k >= 0 && k < KSIZE) a3 = fmaf(w[k], xv, a3); }
                }
            }

            *reinterpret_cast<float4*>(&yseg[4 * g]) =
                make_float4(a0, a1, a2, a3);
        }
    }
}

extern "C" void kernel_launch(void* const* d_in, const int* in_sizes, int n_in,
                              void* d_out, int out_size)
{
    const float* x     = (const float*)d_in[0];
    const float* alpha = (const float*)d_in[1];
    const float* beta  = (const float*)d_in[2];
    const float* theta = (const float*)d_in[3];
    float* y = (float*)d_out;

    const int rows = in_sizes[0] / T_LEN;   // B*C = 16384
    ssm4d_conv_kernel<<<rows * 2, THREADS>>>(x, alpha, beta, theta, y);
}

// round 12
// speedup vs baseline: 1.8220x; 1.0312x over previous
#include <cuda_runtime.h>
#include <math.h>
#include <stdint.h>

#define T_LEN    3000
#define C_CH     1024
#define KSIZE    24
#define SEG      1500          // outputs per CTA (half a row)
#define THREADS  128
#define NGROUP   (SEG / 4)     // 375 groups of 4 consecutive outputs

// Layout: s[i] = x[segBase + i - 24]; s[0..23] halo chunk region (s[0]
// carries x[segBase-24]: real data for half=1, zero for half=0; never read
// by compute), data s[24..1523]. Output 4g+j = sum_k w[k]*s[4g+(k+j+1)];
// group g reads float4 chunks g..g+6 -- all 16B-aligned, affine offsets.
#define SBUF_FLOATS 1536
#define NHALO_CHUNK 6          // chunks 0..5 = s[0..23]
#define DATA_CHUNK0 6          // chunk of s[24]
#define LAST_CHUNK  381        // data chunks 6..380

__global__ __launch_bounds__(THREADS, 12)
void ssm4d_conv_kernel(const float* __restrict__ x,
                       const float* __restrict__ alpha,
                       const float* __restrict__ beta,
                       const float* __restrict__ theta,
                       float* __restrict__ y)
{
    __shared__ __align__(16) float s[SBUF_FLOATS];
    __shared__ __align__(16) float wsh[KSIZE];

    const int row  = blockIdx.x >> 1;        // row = b*C + c
    const int half = blockIdx.x & 1;
    const int c    = row & (C_CH - 1);
    const int tid  = threadIdx.x;

    const float* __restrict__ xseg = x + (size_t)row * T_LEN + half * SEG;
    float* __restrict__       yseg = y + (size_t)row * T_LEN + half * SEG;

    // Staging: 381 aligned 16B chunks. Chunks 0..5 = halo (cp.async from
    // xseg-24 when half=1 — in-bounds row data; zeros when half=0);
    // chunks 6..380 = segment data via cp.async (3 per thread).
    {
        uint32_t sa;
        asm("{ .reg .u64 t; cvta.to.shared.u64 t, %1; cvt.u32.u64 %0, t; }"
            : "=r"(sa) : "l"(s));

        if (tid < NHALO_CHUNK) {
            if (half) {
                asm volatile("cp.async.cg.shared.global [%0], [%1], 16;"
                             :: "r"(sa + 16u * tid), "l"(xseg - 24 + 4 * tid));
            } else {
                *reinterpret_cast<float4*>(&s[4 * tid]) =
                    make_float4(0.f, 0.f, 0.f, 0.f);
            }
        }
        #pragma unroll
        for (int u = 0; u < 3; u++) {
            const int ch = DATA_CHUNK0 + tid + u * THREADS;
            if (ch < LAST_CHUNK) {
                asm volatile("cp.async.cg.shared.global [%0], [%1], 16;"
                             :: "r"(sa + 16u * ch),
                                "l"(xseg + 4 * (ch - DATA_CHUNK0)));
            }
        }
        asm volatile("cp.async.commit_group;");
    }

    // Synthesize the 24 depthwise taps for this channel (once per block).
    // w[k] = beta * exp(log(max(alpha,1e-6))*k) * (1 - (theta*k)^2/2 + (theta*k)^4/24)
    if (tid < KSIZE) {
        float a   = fmaxf(alpha[c], 1e-6f);
        float la  = logf(a);
        float k   = (float)tid;
        float dec = expf(la * k);
        float xx  = theta[c] * k;
        float x2  = xx * xx;
        float ph  = 1.0f - 0.5f * x2 + (x2 * x2) * (1.0f / 24.0f);
        wsh[tid]  = beta[c] * dec * ph;
    }

    asm volatile("cp.async.wait_group 0;");
    __syncthreads();

    // Weights to registers: 6 x LDS.128 broadcast (16B-aligned).
    float w[KSIZE];
    #pragma unroll
    for (int k4 = 0; k4 < KSIZE; k4 += 4) {
        float4 wv = *reinterpret_cast<const float4*>(&wsh[k4]);
        w[k4] = wv.x; w[k4+1] = wv.y; w[k4+2] = wv.z; w[k4+3] = wv.w;
    }

    // Each thread: groups g = tid, tid+128, tid+256 (g < 375). 16B lane
    // stride -> every LDS.128 is a contiguous conflict-free 512B warp
    // access; STG.128 stores are perfectly coalesced.
    #pragma unroll
    for (int gi = 0; gi < 3; gi++) {
        const int g = tid + gi * THREADS;
        if (g < NGROUP) {
            const float* sp = &s[4 * g];

            float a0 = 0.f, a1 = 0.f, a2 = 0.f, a3 = 0.f;
            #pragma unroll
            for (int q = 0; q < 7; q++) {
                float4 v = *reinterpret_cast<const float4*>(sp + 4 * q);
                #pragma unroll
                for (int i = 0; i < 4; i++) {
                    const int m = 4 * q + i;            // window index
                    const float xv = (i == 0) ? v.x : (i == 1) ? v.y
                                   : (i == 2) ? v.z : v.w;
                    // acc j uses tap k = m - j - 1, valid for 0 <= k < 24.
                    { const int k = m - 1; if (k >= 0 && k < KSIZE) a0 = fmaf(w[k], xv, a0); }
                    { const int k = m - 2; if (k >= 0 && k < KSIZE) a1 = fmaf(w[k], xv, a1); }
                    { const int k = m - 3; if (k >= 0 && k < KSIZE) a2 = fmaf(w[k], xv, a2); }
                    { const int k = m - 4; if (k >= 0 && k < KSIZE) a3 = fmaf(w[k], xv, a3); }
                }
            }

            *reinterpret_cast<float4*>(&yseg[4 * g]) =
                make_float4(a0, a1, a2, a3);
        }
    }
}

extern "C" void kernel_launch(void* const* d_in, const int* in_sizes, int n_in,
                              void* d_out, int out_size)
{
    const float* x     = (const float*)d_in[0];
    const float* alpha = (const float*)d_in[1];
    const float* beta  = (const float*)d_in[2];
    const float* theta = (const float*)d_in[3];
    float* y = (float*)d_out;

    const int rows = in_sizes[0] / T_LEN;   // B*C = 16384
    ssm4d_conv_kernel<<<rows * 2, THREADS>>>(x, alpha, beta, theta, y);
}